// round 10
// baseline (speedup 1.0000x reference)
#include <cuda_runtime.h>
#include <math.h>
#include <complex>

// e3nn uvw tensor square: 64x0e+32x1o+16x2e -> itself, B=20000.
// Host builds exact real CG (double precision, reference algorithm), passes by
// value. One kernel: 32 rows/CTA (lane=row), 30 warps = 30 (irrep,k,w-slice)
// units, warp-uniform float4 weight loads, shared-memory x with pad 241.

struct CGPack { float c[363]; };

// offsets into CGPack.c
#define O000 0
#define O011 1
#define O022 10
#define O101 35
#define O110 44
#define O112 53
#define O121 98
#define O202 143
#define O211 168
#define O220 213
#define O222 238

// ---------------------------------------------------------------- host CG ---
static double fct(int n) { double r = 1.0; for (int i = 2; i <= n; ++i) r *= i; return r; }

static double su2cg(int j1, int m1, int j2, int m2, int j3, int m3) {
    if (m3 != m1 + m2) return 0.0;
    int vmin = -j1 + j2 + m3; if (-j1 + m1 > vmin) vmin = -j1 + m1; if (0 > vmin) vmin = 0;
    int vmax = j2 + j3 + m1; if (j3 - j1 + j2 < vmax) vmax = j3 - j1 + j2; if (j3 + m3 < vmax) vmax = j3 + m3;
    if (vmax < vmin) return 0.0;
    double C = sqrt((2 * j3 + 1) * fct(j3 + j1 - j2) * fct(j3 - j1 + j2) * fct(j1 + j2 - j3)
                    * fct(j3 + m3) * fct(j3 - m3)
                    / (fct(j1 + j2 + j3 + 1) * fct(j1 - m1) * fct(j1 + m1) * fct(j2 - m2) * fct(j2 + m2)));
    double S = 0.0;
    for (int v = vmin; v <= vmax; ++v) {
        double sgn = ((v + j2 + m2) & 1) ? -1.0 : 1.0;
        S += sgn * fct(j2 + j3 + m1 - v) * fct(j1 - m1 + v)
             / (fct(v) * fct(j3 - j1 + j2 - v) * fct(j3 + m3 - v) * fct(v + j1 - j2 - m3));
    }
    return C * S;
}

typedef std::complex<double> cplx;

static void qmat(int l, cplx* q) {  // (2l+1)x(2l+1) row-major
    int n = 2 * l + 1;
    for (int i = 0; i < n * n; ++i) q[i] = 0.0;
    const double is2 = 1.0 / sqrt(2.0);
    for (int m = -l; m < 0; ++m) {
        q[(l + m) * n + (l - m)] = is2;                 // col l+|m|
        q[(l + m) * n + (l + m)] = cplx(0.0, -is2);     // col l-|m|
    }
    q[l * n + l] = 1.0;
    for (int m = 1; m <= l; ++m) {
        double s = (m & 1) ? -1.0 : 1.0;
        q[(l + m) * n + (l + m)] = s * is2;
        q[(l + m) * n + (l - m)] = cplx(0.0, s * is2);
    }
    cplx ph = 1.0; for (int i = 0; i < l; ++i) ph *= cplx(0.0, -1.0);  // (-1j)^l
    for (int i = 0; i < n * n; ++i) q[i] *= ph;
}

static void real_cg(int l1, int l2, int l3, float* out, double scale) {
    int n1 = 2 * l1 + 1, n2 = 2 * l2 + 1, n3 = 2 * l3 + 1;
    cplx Q1[25], Q2[25], Q3[25];
    qmat(l1, Q1); qmat(l2, Q2); qmat(l3, Q3);
    for (int j = 0; j < n1; ++j)
        for (int lc = 0; lc < n2; ++lc)
            for (int mm = 0; mm < n3; ++mm) {
                cplx s = 0.0;
                for (int i = 0; i < n1; ++i)
                    for (int kk = 0; kk < n2; ++kk) {
                        int m1 = i - l1, m2 = kk - l2, m3 = m1 + m2;
                        if (m3 < -l3 || m3 > l3) continue;
                        double cg = su2cg(l1, m1, l2, m2, l3, m3);
                        if (cg == 0.0) continue;
                        s += Q1[i * n1 + j] * Q2[kk * n2 + lc] * std::conj(Q3[(l3 + m3) * n3 + mm]) * cg;
                    }
                out[(j * n2 + lc) * n3 + mm] = (float)(s.real() * scale);
            }
}

static void build_cg(CGPack& cg) {
    double fan0 = 64.0 * 64 + 32.0 * 32 + 16.0 * 16;                     // 5376
    double fan1 = 64.0 * 32 + 32.0 * 64 + 32.0 * 16 + 16.0 * 32;         // 5120
    double fan2 = 64.0 * 16 + 16.0 * 64 + 32.0 * 32 + 16.0 * 16;         // 3328
    double s0 = sqrt(1.0) / sqrt(fan0);
    double s1 = sqrt(3.0) / sqrt(fan1);
    double s2 = sqrt(5.0) / sqrt(fan2);
    real_cg(0, 0, 0, cg.c + O000, s0);
    real_cg(0, 1, 1, cg.c + O011, s1);
    real_cg(0, 2, 2, cg.c + O022, s2);
    real_cg(1, 0, 1, cg.c + O101, s1);
    real_cg(1, 1, 0, cg.c + O110, s0);
    real_cg(1, 1, 2, cg.c + O112, s2);
    real_cg(1, 2, 1, cg.c + O121, s1);
    real_cg(2, 0, 2, cg.c + O202, s2);
    real_cg(2, 1, 1, cg.c + O211, s1);
    real_cg(2, 2, 0, cg.c + O220, s0);
    real_cg(2, 2, 2, cg.c + O222, s2);
}

// -------------------------------------------------------------- device ------
template <int D1, int D2, int D3, int M1, int M2, int MO>
__device__ __forceinline__ void seg(const float* __restrict__ x1,
                                    const float* __restrict__ x2,
                                    const float* __restrict__ C, int k,
                                    const float* __restrict__ W, int wo,
                                    float acc[8]) {
    const int s4 = MO >> 2;
    for (int u = 0; u < M1; ++u) {
        float c[D2];
#pragma unroll
        for (int j = 0; j < D2; ++j) {
            float s = 0.f;
#pragma unroll
            for (int i = 0; i < D1; ++i) s = fmaf(C[(i * D2 + j) * D3 + k], x1[u * D1 + i], s);
            c[j] = s;
        }
        const float4* Wp = reinterpret_cast<const float4*>(W + (u * M2) * MO + wo);
#pragma unroll 4
        for (int v = 0; v < M2; ++v) {
            float f = 0.f;
#pragma unroll
            for (int j = 0; j < D2; ++j) f = fmaf(c[j], x2[v * D2 + j], f);
            float4 wa = Wp[0];
            float4 wb = Wp[1];
            Wp += s4;
            acc[0] = fmaf(wa.x, f, acc[0]); acc[1] = fmaf(wa.y, f, acc[1]);
            acc[2] = fmaf(wa.z, f, acc[2]); acc[3] = fmaf(wa.w, f, acc[3]);
            acc[4] = fmaf(wb.x, f, acc[4]); acc[5] = fmaf(wb.y, f, acc[5]);
            acc[6] = fmaf(wb.z, f, acc[6]); acc[7] = fmaf(wb.w, f, acc[7]);
        }
    }
}

__global__ __launch_bounds__(960, 1)
void tsq_kernel(const float* __restrict__ x, float* __restrict__ y, int rows,
                const float* __restrict__ W0, const float* __restrict__ W1,
                const float* __restrict__ W2, const float* __restrict__ W3,
                const float* __restrict__ W4, const float* __restrict__ W5,
                const float* __restrict__ W6, const float* __restrict__ W7,
                const float* __restrict__ W8, const float* __restrict__ W9,
                const float* __restrict__ W10, CGPack cg) {
    __shared__ float xs[32 * 241];
    const int tid = threadIdx.x;
    const int rowbase = blockIdx.x * 32;
    int nr = rows - rowbase; if (nr > 32) nr = 32;

    for (int i = tid; i < nr * 240; i += 960)
        xs[(i / 240) * 241 + (i % 240)] = x[(size_t)rowbase * 240 + i];
    if (nr < 32)  // zero-fill tail rows so compute stays finite
        for (int i = nr * 240 + tid; i < 32 * 240; i += 960)
            xs[(i / 240) * 241 + (i % 240)] = 0.f;
    __syncthreads();

    const int wid = tid >> 5, lane = tid & 31;
    const float* xr = xs + lane * 241;
    const float* x0g = xr;          // 64 x (l=0)
    const float* x1g = xr + 64;     // 32 x (l=1)
    const float* x2g = xr + 160;    // 16 x (l=2)

    float acc[8] = {0.f, 0.f, 0.f, 0.f, 0.f, 0.f, 0.f, 0.f};
    int k = 0, wo = 0;

    if (wid < 8) {                                   // out irrep 0: 64x0e
        wo = wid * 8;
        seg<1, 1, 1, 64, 64, 64>(x0g, x0g, cg.c + O000, 0, W0, wo, acc);
        seg<3, 3, 1, 32, 32, 64>(x1g, x1g, cg.c + O110, 0, W4, wo, acc);
        seg<5, 5, 1, 16, 16, 64>(x2g, x2g, cg.c + O220, 0, W9, wo, acc);
    } else if (wid < 20) {                           // out irrep 1: 32x1o
        int u = wid - 8; k = u >> 2; wo = (u & 3) * 8;
        seg<1, 3, 3, 64, 32, 32>(x0g, x1g, cg.c + O011, k, W1, wo, acc);
        seg<3, 1, 3, 32, 64, 32>(x1g, x0g, cg.c + O101, k, W3, wo, acc);
        seg<3, 5, 3, 32, 16, 32>(x1g, x2g, cg.c + O121, k, W6, wo, acc);
        seg<5, 3, 3, 16, 32, 32>(x2g, x1g, cg.c + O211, k, W8, wo, acc);
    } else {                                         // out irrep 2: 16x2e
        int u = wid - 20; k = u >> 1; wo = (u & 1) * 8;
        seg<1, 5, 5, 64, 16, 16>(x0g, x2g, cg.c + O022, k, W2, wo, acc);
        seg<3, 3, 5, 32, 32, 16>(x1g, x1g, cg.c + O112, k, W5, wo, acc);
        seg<5, 1, 5, 16, 64, 16>(x2g, x0g, cg.c + O202, k, W7, wo, acc);
        seg<5, 5, 5, 16, 16, 16>(x2g, x2g, cg.c + O222, k, W10, wo, acc);
    }

    if (lane < nr) {
        float* yr = y + (size_t)(rowbase + lane) * 240;
        if (wid < 8) {
#pragma unroll
            for (int t = 0; t < 8; ++t) yr[wo + t] = acc[t];
        } else if (wid < 20) {
#pragma unroll
            for (int t = 0; t < 8; ++t) yr[64 + (wo + t) * 3 + k] = acc[t];
        } else {
#pragma unroll
            for (int t = 0; t < 8; ++t) yr[160 + (wo + t) * 5 + k] = acc[t];
        }
    }
}

// ---------------------------------------------------------------- launch ----
extern "C" void kernel_launch(void* const* d_in, const int* in_sizes, int n_in,
                              void* d_out, int out_size) {
    (void)n_in; (void)out_size;
    const float* x = (const float*)d_in[0];
    const float* W[11];
    for (int i = 0; i < 11; ++i) W[i] = (const float*)d_in[1 + i];
    int rows = in_sizes[0] / 240;

    CGPack cg;
    build_cg(cg);

    int nblk = (rows + 31) / 32;
    tsq_kernel<<<nblk, 960>>>(x, (float*)d_out, rows,
                              W[0], W[1], W[2], W[3], W[4], W[5],
                              W[6], W[7], W[8], W[9], W[10], cg);
}

// round 11
// speedup vs baseline: 2.1323x; 2.1323x over previous
#include <cuda_runtime.h>
#include <math.h>
#include <complex>

typedef unsigned long long ull;

// ---------------------------------------------------------------- host CG ---
struct CGPack { float c[363]; };
#define O000 0
#define O011 1
#define O022 10
#define O101 35
#define O110 44
#define O112 53
#define O121 98
#define O202 143
#define O211 168
#define O220 213
#define O222 238

static double fct(int n) { double r = 1.0; for (int i = 2; i <= n; ++i) r *= i; return r; }

static double su2cg(int j1, int m1, int j2, int m2, int j3, int m3) {
    if (m3 != m1 + m2) return 0.0;
    int vmin = -j1 + j2 + m3; if (-j1 + m1 > vmin) vmin = -j1 + m1; if (0 > vmin) vmin = 0;
    int vmax = j2 + j3 + m1; if (j3 - j1 + j2 < vmax) vmax = j3 - j1 + j2; if (j3 + m3 < vmax) vmax = j3 + m3;
    if (vmax < vmin) return 0.0;
    double C = sqrt((2 * j3 + 1) * fct(j3 + j1 - j2) * fct(j3 - j1 + j2) * fct(j1 + j2 - j3)
                    * fct(j3 + m3) * fct(j3 - m3)
                    / (fct(j1 + j2 + j3 + 1) * fct(j1 - m1) * fct(j1 + m1) * fct(j2 - m2) * fct(j2 + m2)));
    double S = 0.0;
    for (int v = vmin; v <= vmax; ++v) {
        double sgn = ((v + j2 + m2) & 1) ? -1.0 : 1.0;
        S += sgn * fct(j2 + j3 + m1 - v) * fct(j1 - m1 + v)
             / (fct(v) * fct(j3 - j1 + j2 - v) * fct(j3 + m3 - v) * fct(v + j1 - j2 - m3));
    }
    return C * S;
}

typedef std::complex<double> cplx;

static void qmat(int l, cplx* q) {
    int n = 2 * l + 1;
    for (int i = 0; i < n * n; ++i) q[i] = 0.0;
    const double is2 = 1.0 / sqrt(2.0);
    for (int m = -l; m < 0; ++m) {
        q[(l + m) * n + (l - m)] = is2;
        q[(l + m) * n + (l + m)] = cplx(0.0, -is2);
    }
    q[l * n + l] = 1.0;
    for (int m = 1; m <= l; ++m) {
        double s = (m & 1) ? -1.0 : 1.0;
        q[(l + m) * n + (l + m)] = s * is2;
        q[(l + m) * n + (l - m)] = cplx(0.0, s * is2);
    }
    cplx ph = 1.0; for (int i = 0; i < l; ++i) ph *= cplx(0.0, -1.0);
    for (int i = 0; i < n * n; ++i) q[i] *= ph;
}

static void real_cg(int l1, int l2, int l3, float* out, double scale) {
    int n1 = 2 * l1 + 1, n2 = 2 * l2 + 1, n3 = 2 * l3 + 1;
    cplx Q1[25], Q2[25], Q3[25];
    qmat(l1, Q1); qmat(l2, Q2); qmat(l3, Q3);
    for (int j = 0; j < n1; ++j)
        for (int lc = 0; lc < n2; ++lc)
            for (int mm = 0; mm < n3; ++mm) {
                cplx s = 0.0;
                for (int i = 0; i < n1; ++i)
                    for (int kk = 0; kk < n2; ++kk) {
                        int m1 = i - l1, m2 = kk - l2, m3 = m1 + m2;
                        if (m3 < -l3 || m3 > l3) continue;
                        double cg = su2cg(l1, m1, l2, m2, l3, m3);
                        if (cg == 0.0) continue;
                        s += Q1[i * n1 + j] * Q2[kk * n2 + lc] * std::conj(Q3[(l3 + m3) * n3 + mm]) * cg;
                    }
                out[(j * n2 + lc) * n3 + mm] = (float)(s.real() * scale);
            }
}

static void build_cg(CGPack& cg) {
    double fan0 = 64.0 * 64 + 32.0 * 32 + 16.0 * 16;
    double fan1 = 64.0 * 32 + 32.0 * 64 + 32.0 * 16 + 16.0 * 32;
    double fan2 = 64.0 * 16 + 16.0 * 64 + 32.0 * 32 + 16.0 * 16;
    double s0 = 1.0 / sqrt(fan0);
    double s1 = sqrt(3.0) / sqrt(fan1);
    double s2 = sqrt(5.0) / sqrt(fan2);
    real_cg(0, 0, 0, cg.c + O000, s0);
    real_cg(0, 1, 1, cg.c + O011, s1);
    real_cg(0, 2, 2, cg.c + O022, s2);
    real_cg(1, 0, 1, cg.c + O101, s1);
    real_cg(1, 1, 0, cg.c + O110, s0);
    real_cg(1, 1, 2, cg.c + O112, s2);
    real_cg(1, 2, 1, cg.c + O121, s1);
    real_cg(2, 0, 2, cg.c + O202, s2);
    real_cg(2, 1, 1, cg.c + O211, s1);
    real_cg(2, 2, 0, cg.c + O220, s0);
    real_cg(2, 2, 2, cg.c + O222, s2);
}

// --------------------------------------------------- packed merged weights --
// G layout: [feature][w], feature order == main-kernel loop order exactly.
__device__ __align__(16) float g_G0[2744 * 64];  // tri64 + tri32 + tri16
__device__ __align__(16) float g_G1[2560 * 32];  // 32x64 (0x1 merged) + 16x32 (1x2 merged)
__device__ __align__(16) float g_G2[1688 * 16];  // 16x64 (0x2 merged) + tri32 + tri16

__global__ void prep_g0(const float* __restrict__ W0, const float* __restrict__ W4,
                        const float* __restrict__ W9) {
    int i = blockIdx.x * blockDim.x + threadIdx.x;
    if (i >= 2744 * 64) return;
    int f = i >> 6, w = i & 63;
    float val;
    if (f < 2080) {
        int t = f, u = 0; while (t >= 64 - u) { t -= 64 - u; ++u; } int v = u + t;
        val = W0[(u * 64 + v) * 64 + w];
        if (v != u) val += W0[(v * 64 + u) * 64 + w];
    } else if (f < 2608) {
        int t = f - 2080, u = 0; while (t >= 32 - u) { t -= 32 - u; ++u; } int v = u + t;
        val = W4[(u * 32 + v) * 64 + w];
        if (v != u) val += W4[(v * 32 + u) * 64 + w];
    } else {
        int t = f - 2608, u = 0; while (t >= 16 - u) { t -= 16 - u; ++u; } int v = u + t;
        val = W9[(u * 16 + v) * 64 + w];
        if (v != u) val += W9[(v * 16 + u) * 64 + w];
    }
    g_G0[i] = val;
}

__global__ void prep_g1(const float* __restrict__ W1, const float* __restrict__ W3,
                        const float* __restrict__ W6, const float* __restrict__ W8) {
    int i = blockIdx.x * blockDim.x + threadIdx.x;
    if (i >= 2560 * 32) return;
    int f = i >> 5, w = i & 31;
    float val;
    if (f < 2048) {              // outer v1 (32) x inner u0 (64): feat = v*64+u
        int v = f >> 6, u = f & 63;
        val = W1[(u * 32 + v) * 32 + w] + W3[(v * 64 + u) * 32 + w];
    } else {                     // outer v2 (16) x inner u1 (32): feat = v*32+u
        int t = f - 2048; int v = t >> 5, u = t & 31;
        val = W6[(u * 16 + v) * 32 + w] + W8[(v * 32 + u) * 32 + w];
    }
    g_G1[i] = val;
}

__global__ void prep_g2(const float* __restrict__ W2, const float* __restrict__ W5,
                        const float* __restrict__ W7, const float* __restrict__ W10) {
    int i = blockIdx.x * blockDim.x + threadIdx.x;
    if (i >= 1688 * 16) return;
    int f = i >> 4, w = i & 15;
    float val;
    if (f < 1024) {              // outer v2 (16) x inner u0 (64): feat = v*64+u
        int v = f >> 6, u = f & 63;
        val = W2[(u * 16 + v) * 16 + w] + W7[(v * 64 + u) * 16 + w];
    } else if (f < 1552) {
        int t = f - 1024, u = 0; while (t >= 32 - u) { t -= 32 - u; ++u; } int v = u + t;
        val = W5[(u * 32 + v) * 16 + w];
        if (v != u) val += W5[(v * 32 + u) * 16 + w];
    } else {
        int t = f - 1552, u = 0; while (t >= 16 - u) { t -= 16 - u; ++u; } int v = u + t;
        val = W10[(u * 16 + v) * 16 + w];
        if (v != u) val += W10[(v * 16 + u) * 16 + w];
    }
    g_G2[i] = val;
}

// -------------------------------------------------------------- f32x2 ops ---
__device__ __forceinline__ ull fma2(ull a, ull b, ull c) {
    ull d; asm("fma.rn.f32x2 %0, %1, %2, %3;" : "=l"(d) : "l"(a), "l"(b), "l"(c)); return d;
}
__device__ __forceinline__ ull mul2(ull a, ull b) {
    ull d; asm("mul.rn.f32x2 %0, %1, %2;" : "=l"(d) : "l"(a), "l"(b)); return d;
}
__device__ __forceinline__ ull bc2(float s) {
    ull d; asm("mov.b64 %0, {%1, %1};" : "=l"(d) : "f"(s)); return d;
}
__device__ __forceinline__ ull ld2(const float* p) { return *reinterpret_cast<const ull*>(p); }

// acc: a[0..3] = row0 outputs packed as w-pairs, a[4..7] = row1.
__device__ __forceinline__ void acc8(ull f, const float* __restrict__ Gp, ull* a) {
    unsigned lo, hi;
    asm("mov.b64 {%0, %1}, %2;" : "=r"(lo), "=r"(hi) : "l"(f));
    ull fl, fh;
    asm("mov.b64 %0, {%1, %1};" : "=l"(fl) : "r"(lo));
    asm("mov.b64 %0, {%1, %1};" : "=l"(fh) : "r"(hi));
    ulonglong2 wa = *reinterpret_cast<const ulonglong2*>(Gp);
    ulonglong2 wb = *reinterpret_cast<const ulonglong2*>(Gp + 4);
    a[0] = fma2(wa.x, fl, a[0]); a[1] = fma2(wa.y, fl, a[1]);
    a[2] = fma2(wb.x, fl, a[2]); a[3] = fma2(wb.y, fl, a[3]);
    a[4] = fma2(wa.x, fh, a[4]); a[5] = fma2(wa.y, fh, a[5]);
    a[6] = fma2(wb.x, fh, a[6]); a[7] = fma2(wb.y, fh, a[7]);
}

// Symmetric x (x) x path, triangular u<=v. xb points at this irrep's block
// (already lane-offset). Feature order: u-major, v from u.
template <int D, int D3, int M, int WS>
__device__ __forceinline__ void tri(const float* __restrict__ xb,
                                    const float* __restrict__ C, int k,
                                    const float*& Gp, ull* acc) {
    for (int u = 0; u < M; ++u) {
        ull c[D];
#pragma unroll
        for (int j = 0; j < D; ++j) {
            ull s = 0ull;
#pragma unroll
            for (int i = 0; i < D; ++i)
                s = fma2(bc2(C[(i * D + j) * D3 + k]), ld2(xb + (u * D + i) * 64), s);
            c[j] = s;
        }
        for (int v = u; v < M; ++v) {
            ull f = mul2(c[0], ld2(xb + (v * D) * 64));
#pragma unroll
            for (int j = 1; j < D; ++j)
                f = fma2(c[j], ld2(xb + (v * D + j) * 64), f);
            acc8(f, Gp, acc);
            Gp += WS;
        }
    }
}

// Rectangular merged path. Inner operand = DI-dim side (fewest LDS per iter),
// outer = DO side (its CG contraction hoisted). Feature order: v-major.
template <int DI, int DO, int D3, int MI, int MO_, int WS>
__device__ __forceinline__ void rect(const float* __restrict__ xi,
                                     const float* __restrict__ xo,
                                     const float* __restrict__ C, int k,
                                     const float*& Gp, ull* acc) {
    for (int v = 0; v < MO_; ++v) {
        ull g[DI];
#pragma unroll
        for (int i = 0; i < DI; ++i) {
            ull s = 0ull;
#pragma unroll
            for (int j = 0; j < DO; ++j)
                s = fma2(bc2(C[(i * DO + j) * D3 + k]), ld2(xo + (v * DO + j) * 64), s);
            g[i] = s;
        }
#pragma unroll 4
        for (int u = 0; u < MI; ++u) {
            ull f = mul2(g[0], ld2(xi + (u * DI) * 64));
#pragma unroll
            for (int i = 1; i < DI; ++i)
                f = fma2(g[i], ld2(xi + (u * DI + i) * 64), f);
            acc8(f, Gp, acc);
            Gp += WS;
        }
    }
}

// ---------------------------------------------------------------- main ------
__global__ __launch_bounds__(480, 2)
void tsq_main(const float* __restrict__ x, float* __restrict__ y, int rows, CGPack cg) {
    extern __shared__ float xs[];   // [240 features][64 rows]
    const int tid = threadIdx.x;
    const int rowbase = blockIdx.x * 64;
    int nr = rows - rowbase; if (nr > 64) nr = 64;

    for (int i = tid; i < 240 * 64; i += 480) {
        int r = i & 63, f = i >> 6;
        xs[i] = (r < nr) ? x[(size_t)(rowbase + r) * 240 + f] : 0.f;
    }
    __syncthreads();

    const int wid = tid >> 5;
    const int lane2 = (tid & 31) << 1;           // rows (lane2, lane2+1)
    const float* x0b = xs + lane2;               // l=0 block: feat 0..63
    const float* x1b = xs + 64 * 64 + lane2;     // l=1 block: feat 64..159
    const float* x2b = xs + 160 * 64 + lane2;    // l=2 block: feat 160..239

    for (int unit = wid; unit < 30; unit += 15) {
        ull acc[8] = {0ull, 0ull, 0ull, 0ull, 0ull, 0ull, 0ull, 0ull};
        int k = 0, wo = 0;
        const float* Gp;
        if (unit < 8) {                          // out irrep 0 (64x0e)
            wo = unit * 8;
            Gp = g_G0 + wo;
            tri<1, 1, 64, 64>(x0b, cg.c + O000, 0, Gp, acc);
            tri<3, 1, 32, 64>(x1b, cg.c + O110, 0, Gp, acc);
            tri<5, 1, 16, 64>(x2b, cg.c + O220, 0, Gp, acc);
        } else if (unit < 20) {                  // out irrep 1 (32x1o)
            int t = unit - 8; k = t >> 2; wo = (t & 3) * 8;
            Gp = g_G1 + wo;
            rect<1, 3, 3, 64, 32, 32>(x0b, x1b, cg.c + O011, k, Gp, acc);
            rect<3, 5, 3, 32, 16, 32>(x1b, x2b, cg.c + O121, k, Gp, acc);
        } else {                                 // out irrep 2 (16x2e)
            int t = unit - 20; k = t >> 1; wo = (t & 1) * 8;
            Gp = g_G2 + wo;
            rect<1, 5, 5, 64, 16, 16>(x0b, x2b, cg.c + O022, k, Gp, acc);
            tri<3, 5, 32, 16>(x1b, cg.c + O112, k, Gp, acc);
            tri<5, 5, 16, 16>(x2b, cg.c + O222, k, Gp, acc);
        }

        float out0[8], out1[8];
#pragma unroll
        for (int t2 = 0; t2 < 4; ++t2) {
            unsigned lo, hi;
            asm("mov.b64 {%0, %1}, %2;" : "=r"(lo), "=r"(hi) : "l"(acc[t2]));
            out0[2 * t2] = __uint_as_float(lo); out0[2 * t2 + 1] = __uint_as_float(hi);
            asm("mov.b64 {%0, %1}, %2;" : "=r"(lo), "=r"(hi) : "l"(acc[t2 + 4]));
            out1[2 * t2] = __uint_as_float(lo); out1[2 * t2 + 1] = __uint_as_float(hi);
        }
        const int r0 = lane2, r1 = lane2 + 1;
        float* y0 = y + (size_t)(rowbase + r0) * 240;
        float* y1 = y + (size_t)(rowbase + r1) * 240;
#pragma unroll
        for (int t2 = 0; t2 < 8; ++t2) {
            int col = (unit < 8) ? (wo + t2)
                    : (unit < 20) ? (64 + (wo + t2) * 3 + k)
                                  : (160 + (wo + t2) * 5 + k);
            if (r0 < nr) y0[col] = out0[t2];
            if (r1 < nr) y1[col] = out1[t2];
        }
    }
}

// ---------------------------------------------------------------- launch ----
extern "C" void kernel_launch(void* const* d_in, const int* in_sizes, int n_in,
                              void* d_out, int out_size) {
    (void)n_in; (void)out_size;
    const float* x = (const float*)d_in[0];
    const float* W[11];
    for (int i = 0; i < 11; ++i) W[i] = (const float*)d_in[1 + i];
    int rows = in_sizes[0] / 240;

    CGPack cg;
    build_cg(cg);

    prep_g0<<<(2744 * 64 + 255) / 256, 256>>>(W[0], W[4], W[9]);
    prep_g1<<<(2560 * 32 + 255) / 256, 256>>>(W[1], W[3], W[6], W[8]);
    prep_g2<<<(1688 * 16 + 255) / 256, 256>>>(W[2], W[5], W[7], W[10]);

    const int smem = 240 * 64 * sizeof(float);   // 61440 B
    cudaFuncSetAttribute(tsq_main, cudaFuncAttributeMaxDynamicSharedMemorySize, smem);
    int nblk = (rows + 63) / 64;
    tsq_main<<<nblk, 480, smem>>>(x, (float*)d_out, rows, cg);
}

// round 12
// speedup vs baseline: 2.8724x; 1.3471x over previous
#include <cuda_runtime.h>
#include <math.h>
#include <complex>

typedef unsigned long long ull;

// ---------------------------------------------------------------- host CG ---
struct CGPack { float c[363]; };
#define O000 0
#define O011 1
#define O022 10
#define O101 35
#define O110 44
#define O112 53
#define O121 98
#define O202 143
#define O211 168
#define O220 213
#define O222 238

static double fct(int n) { double r = 1.0; for (int i = 2; i <= n; ++i) r *= i; return r; }

static double su2cg(int j1, int m1, int j2, int m2, int j3, int m3) {
    if (m3 != m1 + m2) return 0.0;
    int vmin = -j1 + j2 + m3; if (-j1 + m1 > vmin) vmin = -j1 + m1; if (0 > vmin) vmin = 0;
    int vmax = j2 + j3 + m1; if (j3 - j1 + j2 < vmax) vmax = j3 - j1 + j2; if (j3 + m3 < vmax) vmax = j3 + m3;
    if (vmax < vmin) return 0.0;
    double C = sqrt((2 * j3 + 1) * fct(j3 + j1 - j2) * fct(j3 - j1 + j2) * fct(j1 + j2 - j3)
                    * fct(j3 + m3) * fct(j3 - m3)
                    / (fct(j1 + j2 + j3 + 1) * fct(j1 - m1) * fct(j1 + m1) * fct(j2 - m2) * fct(j2 + m2)));
    double S = 0.0;
    for (int v = vmin; v <= vmax; ++v) {
        double sgn = ((v + j2 + m2) & 1) ? -1.0 : 1.0;
        S += sgn * fct(j2 + j3 + m1 - v) * fct(j1 - m1 + v)
             / (fct(v) * fct(j3 - j1 + j2 - v) * fct(j3 + m3 - v) * fct(v + j1 - j2 - m3));
    }
    return C * S;
}

typedef std::complex<double> cplx;

static void qmat(int l, cplx* q) {
    int n = 2 * l + 1;
    for (int i = 0; i < n * n; ++i) q[i] = 0.0;
    const double is2 = 1.0 / sqrt(2.0);
    for (int m = -l; m < 0; ++m) {
        q[(l + m) * n + (l - m)] = is2;
        q[(l + m) * n + (l + m)] = cplx(0.0, -is2);
    }
    q[l * n + l] = 1.0;
    for (int m = 1; m <= l; ++m) {
        double s = (m & 1) ? -1.0 : 1.0;
        q[(l + m) * n + (l + m)] = s * is2;
        q[(l + m) * n + (l - m)] = cplx(0.0, s * is2);
    }
    cplx ph = 1.0; for (int i = 0; i < l; ++i) ph *= cplx(0.0, -1.0);
    for (int i = 0; i < n * n; ++i) q[i] *= ph;
}

static void real_cg(int l1, int l2, int l3, float* out, double scale) {
    int n1 = 2 * l1 + 1, n2 = 2 * l2 + 1, n3 = 2 * l3 + 1;
    cplx Q1[25], Q2[25], Q3[25];
    qmat(l1, Q1); qmat(l2, Q2); qmat(l3, Q3);
    for (int j = 0; j < n1; ++j)
        for (int lc = 0; lc < n2; ++lc)
            for (int mm = 0; mm < n3; ++mm) {
                cplx s = 0.0;
                for (int i = 0; i < n1; ++i)
                    for (int kk = 0; kk < n2; ++kk) {
                        int m1 = i - l1, m2 = kk - l2, m3 = m1 + m2;
                        if (m3 < -l3 || m3 > l3) continue;
                        double cg = su2cg(l1, m1, l2, m2, l3, m3);
                        if (cg == 0.0) continue;
                        s += Q1[i * n1 + j] * Q2[kk * n2 + lc] * std::conj(Q3[(l3 + m3) * n3 + mm]) * cg;
                    }
                out[(j * n2 + lc) * n3 + mm] = (float)(s.real() * scale);
            }
}

static void build_cg(CGPack& cg) {
    double fan0 = 64.0 * 64 + 32.0 * 32 + 16.0 * 16;
    double fan1 = 64.0 * 32 + 32.0 * 64 + 32.0 * 16 + 16.0 * 32;
    double fan2 = 64.0 * 16 + 16.0 * 64 + 32.0 * 32 + 16.0 * 16;
    double s0 = 1.0 / sqrt(fan0);
    double s1 = sqrt(3.0) / sqrt(fan1);
    double s2 = sqrt(5.0) / sqrt(fan2);
    real_cg(0, 0, 0, cg.c + O000, s0);
    real_cg(0, 1, 1, cg.c + O011, s1);
    real_cg(0, 2, 2, cg.c + O022, s2);
    real_cg(1, 0, 1, cg.c + O101, s1);
    real_cg(1, 1, 0, cg.c + O110, s0);
    real_cg(1, 1, 2, cg.c + O112, s2);
    real_cg(1, 2, 1, cg.c + O121, s1);
    real_cg(2, 0, 2, cg.c + O202, s2);
    real_cg(2, 1, 1, cg.c + O211, s1);
    real_cg(2, 2, 0, cg.c + O220, s0);
    real_cg(2, 2, 2, cg.c + O222, s2);
}

// --------------------------------------------------- packed merged weights --
// Layout [feature][w], feature order == main-kernel traversal order.
// +64 floats pad: the software prefetch reads one W-row past each array end.
#define NG0 (2744 * 64)
#define NG1 (2560 * 32)
#define NG2 (1688 * 16)
__device__ __align__(16) float g_G0[NG0 + 64];
__device__ __align__(16) float g_G1[NG1 + 64];
__device__ __align__(16) float g_G2[NG2 + 64];

__global__ void prep_all(const float* __restrict__ W0, const float* __restrict__ W1,
                         const float* __restrict__ W2, const float* __restrict__ W3,
                         const float* __restrict__ W4, const float* __restrict__ W5,
                         const float* __restrict__ W6, const float* __restrict__ W7,
                         const float* __restrict__ W8, const float* __restrict__ W9,
                         const float* __restrict__ W10, float c000) {
    int i = blockIdx.x * blockDim.x + threadIdx.x;
    if (i < NG0) {
        int f = i >> 6, w = i & 63;
        float val;
        if (f < 2080) {
            int t = f, u = 0; while (t >= 64 - u) { t -= 64 - u; ++u; } int v = u + t;
            val = W0[(u * 64 + v) * 64 + w];
            if (v != u) val += W0[(v * 64 + u) * 64 + w];
            val *= c000;   // fold scalar CG of the 0x0->0 path
        } else if (f < 2608) {
            int t = f - 2080, u = 0; while (t >= 32 - u) { t -= 32 - u; ++u; } int v = u + t;
            val = W4[(u * 32 + v) * 64 + w];
            if (v != u) val += W4[(v * 32 + u) * 64 + w];
        } else {
            int t = f - 2608, u = 0; while (t >= 16 - u) { t -= 16 - u; ++u; } int v = u + t;
            val = W9[(u * 16 + v) * 64 + w];
            if (v != u) val += W9[(v * 16 + u) * 64 + w];
        }
        g_G0[i] = val;
        return;
    }
    i -= NG0;
    if (i < NG1) {
        int f = i >> 5, w = i & 31;
        float val;
        if (f < 2048) {              // outer v1 (32) x inner u0 (64)
            int v = f >> 6, u = f & 63;
            val = W1[(u * 32 + v) * 32 + w] + W3[(v * 64 + u) * 32 + w];
        } else {                     // outer v2 (16) x inner u1 (32)
            int t = f - 2048; int v = t >> 5, u = t & 31;
            val = W6[(u * 16 + v) * 32 + w] + W8[(v * 32 + u) * 32 + w];
        }
        g_G1[i] = val;
        return;
    }
    i -= NG1;
    if (i < NG2) {
        int f = i >> 4, w = i & 15;
        float val;
        if (f < 1024) {              // outer v2 (16) x inner u0 (64)
            int v = f >> 6, u = f & 63;
            val = W2[(u * 16 + v) * 16 + w] + W7[(v * 64 + u) * 16 + w];
        } else if (f < 1552) {
            int t = f - 1024, u = 0; while (t >= 32 - u) { t -= 32 - u; ++u; } int v = u + t;
            val = W5[(u * 32 + v) * 16 + w];
            if (v != u) val += W5[(v * 32 + u) * 16 + w];
        } else {
            int t = f - 1552, u = 0; while (t >= 16 - u) { t -= 16 - u; ++u; } int v = u + t;
            val = W10[(u * 16 + v) * 16 + w];
            if (v != u) val += W10[(v * 16 + u) * 16 + w];
        }
        g_G2[i] = val;
    }
}

// -------------------------------------------------------------- f32x2 ops ---
__device__ __forceinline__ ull fma2(ull a, ull b, ull c) {
    ull d; asm("fma.rn.f32x2 %0, %1, %2, %3;" : "=l"(d) : "l"(a), "l"(b), "l"(c)); return d;
}
__device__ __forceinline__ ull mul2(ull a, ull b) {
    ull d; asm("mul.rn.f32x2 %0, %1, %2;" : "=l"(d) : "l"(a), "l"(b)); return d;
}
__device__ __forceinline__ ull bc2(float s) {
    ull d; asm("mov.b64 %0, {%1, %1};" : "=l"(d) : "f"(s)); return d;
}
__device__ __forceinline__ ull ld2(const float* p) { return *reinterpret_cast<const ull*>(p); }

__device__ __forceinline__ void splitbc(ull f, ull& fl, ull& fh) {
    unsigned lo, hi;
    asm("mov.b64 {%0, %1}, %2;" : "=r"(lo), "=r"(hi) : "l"(f));
    asm("mov.b64 %0, {%1, %1};" : "=l"(fl) : "r"(lo));
    asm("mov.b64 %0, {%1, %1};" : "=l"(fh) : "r"(hi));
}

__device__ __forceinline__ void acc8(ull fl, ull fh, ulonglong2 wa, ulonglong2 wb, ull* a) {
    a[0] = fma2(wa.x, fl, a[0]); a[1] = fma2(wa.y, fl, a[1]);
    a[2] = fma2(wb.x, fl, a[2]); a[3] = fma2(wb.y, fl, a[3]);
    a[4] = fma2(wa.x, fh, a[4]); a[5] = fma2(wa.y, fh, a[5]);
    a[6] = fma2(wb.x, fh, a[6]); a[7] = fma2(wb.y, fh, a[7]);
}

// Symmetric path, triangular u<=v. D==1: CG folded into G at prep.
template <int D, int D3, int M, int WS>
__device__ __forceinline__ void tri(const float* __restrict__ xb,
                                    const float* __restrict__ C, int k,
                                    const float*& Gp, ull* acc) {
    ulonglong2 wa = *reinterpret_cast<const ulonglong2*>(Gp);
    ulonglong2 wb = *reinterpret_cast<const ulonglong2*>(Gp + 4);
    for (int u = 0; u < M; ++u) {
        ull c[D];
        if (D == 1) {
            c[0] = ld2(xb + u * 64);
        } else {
#pragma unroll
            for (int j = 0; j < D; ++j) {
                ull s = mul2(bc2(C[j * D3 + k]), ld2(xb + (u * D) * 64));
#pragma unroll
                for (int i = 1; i < D; ++i)
                    s = fma2(bc2(C[(i * D + j) * D3 + k]), ld2(xb + (u * D + i) * 64), s);
                c[j] = s;
            }
        }
        for (int v = u; v < M; ++v) {
            ull f = mul2(c[0], ld2(xb + (v * D) * 64));
#pragma unroll
            for (int j = 1; j < D; ++j)
                f = fma2(c[j], ld2(xb + (v * D + j) * 64), f);
            Gp += WS;                                        // prefetch next W row
            ulonglong2 na = *reinterpret_cast<const ulonglong2*>(Gp);
            ulonglong2 nb = *reinterpret_cast<const ulonglong2*>(Gp + 4);
            ull fl, fh; splitbc(f, fl, fh);
            acc8(fl, fh, wa, wb, acc);
            wa = na; wb = nb;
        }
    }
}

// Rectangular merged path: inner = DI side (fewest LDS/iter), outer = DO side.
template <int DI, int DO, int D3, int MI, int MO_, int WS>
__device__ __forceinline__ void rect(const float* __restrict__ xi,
                                     const float* __restrict__ xo,
                                     const float* __restrict__ C, int k,
                                     const float*& Gp, ull* acc) {
    ulonglong2 wa = *reinterpret_cast<const ulonglong2*>(Gp);
    ulonglong2 wb = *reinterpret_cast<const ulonglong2*>(Gp + 4);
    for (int v = 0; v < MO_; ++v) {
        ull g[DI];
#pragma unroll
        for (int i = 0; i < DI; ++i) {
            ull s = mul2(bc2(C[(i * DO) * D3 + k]), ld2(xo + (v * DO) * 64));
#pragma unroll
            for (int j = 1; j < DO; ++j)
                s = fma2(bc2(C[(i * DO + j) * D3 + k]), ld2(xo + (v * DO + j) * 64), s);
            g[i] = s;
        }
        for (int u = 0; u < MI; ++u) {
            ull f = mul2(g[0], ld2(xi + (u * DI) * 64));
#pragma unroll
            for (int i = 1; i < DI; ++i)
                f = fma2(g[i], ld2(xi + (u * DI + i) * 64), f);
            Gp += WS;
            ulonglong2 na = *reinterpret_cast<const ulonglong2*>(Gp);
            ulonglong2 nb = *reinterpret_cast<const ulonglong2*>(Gp + 4);
            ull fl, fh; splitbc(f, fl, fh);
            acc8(fl, fh, wa, wb, acc);
            wa = na; wb = nb;
        }
    }
}

// ---------------------------------------------------------------- main ------
__global__ __launch_bounds__(480, 2)
void tsq_main(const float* __restrict__ x, float* __restrict__ y, int rows, CGPack cg) {
    extern __shared__ float xs[];   // [240 features][64 rows]
    const int tid = threadIdx.x;
    const int rowbase = blockIdx.x * 64;
    int nr = rows - rowbase; if (nr > 64) nr = 64;

    for (int i = tid; i < 240 * 64; i += 480) {
        int r = i & 63, f = i >> 6;
        xs[i] = (r < nr) ? x[(size_t)(rowbase + r) * 240 + f] : 0.f;
    }
    __syncthreads();

    const int wid = tid >> 5;
    const int lane2 = (tid & 31) << 1;           // rows (lane2, lane2+1)
    const float* x0b = xs + lane2;               // l=0: feat 0..63
    const float* x1b = xs + 64 * 64 + lane2;     // l=1: feat 64..159
    const float* x2b = xs + 160 * 64 + lane2;    // l=2: feat 160..239

    // balanced pairing: heavy irrep0 with light irrep2; irrep1 together
    const int u0 = (wid < 8) ? wid : (wid < 14 ? 8 + 2 * (wid - 8) : 28);
    const int u1 = (wid < 8) ? 20 + wid : (wid < 14 ? 9 + 2 * (wid - 8) : 29);

#pragma unroll
    for (int t = 0; t < 2; ++t) {
        const int unit = t ? u1 : u0;
        ull acc[8] = {0ull, 0ull, 0ull, 0ull, 0ull, 0ull, 0ull, 0ull};
        int k = 0, wo = 0;
        const float* Gp;
        if (unit < 8) {                          // out irrep 0 (64x0e)
            wo = unit * 8;
            Gp = g_G0 + wo;
            tri<1, 1, 64, 64>(x0b, cg.c + O000, 0, Gp, acc);
            tri<3, 1, 32, 64>(x1b, cg.c + O110, 0, Gp, acc);
            tri<5, 1, 16, 64>(x2b, cg.c + O220, 0, Gp, acc);
        } else if (unit < 20) {                  // out irrep 1 (32x1o)
            int q = unit - 8; k = q >> 2; wo = (q & 3) * 8;
            Gp = g_G1 + wo;
            rect<1, 3, 3, 64, 32, 32>(x0b, x1b, cg.c + O011, k, Gp, acc);
            rect<3, 5, 3, 32, 16, 32>(x1b, x2b, cg.c + O121, k, Gp, acc);
        } else {                                 // out irrep 2 (16x2e)
            int q = unit - 20; k = q >> 1; wo = (q & 1) * 8;
            Gp = g_G2 + wo;
            rect<1, 5, 5, 64, 16, 16>(x0b, x2b, cg.c + O022, k, Gp, acc);
            tri<3, 5, 32, 16>(x1b, cg.c + O112, k, Gp, acc);
            tri<5, 5, 16, 16>(x2b, cg.c + O222, k, Gp, acc);
        }

        float out0[8], out1[8];
#pragma unroll
        for (int t2 = 0; t2 < 4; ++t2) {
            unsigned lo, hi;
            asm("mov.b64 {%0, %1}, %2;" : "=r"(lo), "=r"(hi) : "l"(acc[t2]));
            out0[2 * t2] = __uint_as_float(lo); out0[2 * t2 + 1] = __uint_as_float(hi);
            asm("mov.b64 {%0, %1}, %2;" : "=r"(lo), "=r"(hi) : "l"(acc[t2 + 4]));
            out1[2 * t2] = __uint_as_float(lo); out1[2 * t2 + 1] = __uint_as_float(hi);
        }
        const int r0 = lane2, r1 = lane2 + 1;
        float* y0 = y + (size_t)(rowbase + r0) * 240;
        float* y1 = y + (size_t)(rowbase + r1) * 240;
#pragma unroll
        for (int t2 = 0; t2 < 8; ++t2) {
            int col = (unit < 8) ? (wo + t2)
                    : (unit < 20) ? (64 + (wo + t2) * 3 + k)
                                  : (160 + (wo + t2) * 5 + k);
            if (r0 < nr) y0[col] = out0[t2];
            if (r1 < nr) y1[col] = out1[t2];
        }
    }
}

// ---------------------------------------------------------------- launch ----
extern "C" void kernel_launch(void* const* d_in, const int* in_sizes, int n_in,
                              void* d_out, int out_size) {
    (void)n_in; (void)out_size;
    const float* x = (const float*)d_in[0];
    const float* W[11];
    for (int i = 0; i < 11; ++i) W[i] = (const float*)d_in[1 + i];
    int rows = in_sizes[0] / 240;

    CGPack cg;
    build_cg(cg);

    const int ntot = NG0 + NG1 + NG2;
    prep_all<<<(ntot + 255) / 256, 256>>>(W[0], W[1], W[2], W[3], W[4], W[5],
                                          W[6], W[7], W[8], W[9], W[10],
                                          cg.c[O000]);

    const int smem = 240 * 64 * sizeof(float);   // 61440 B
    cudaFuncSetAttribute(tsq_main, cudaFuncAttributeMaxDynamicSharedMemorySize, smem);
    int nblk = (rows + 63) / 64;
    tsq_main<<<nblk, 480, smem>>>(x, (float*)d_out, rows, cg);
}